// round 13
// baseline (speedup 1.0000x reference)
#include <cuda_runtime.h>
#include <cuda_bf16.h>
#include <cstdint>
#include <cstddef>

#define S_  2048
#define D_  64
#define H_  16
#define B_  2
#define BH_ 32
#define TQ  128
#define TK  128
#define NKT (S_/TK)
#define TK2 64
#define NKT2 (S_/TK2)

// ---------------- device scratch (allocation-free rule) ----------------
__device__ float g_m[BH_*S_];
__device__ float g_l[BH_*S_];
__device__ float g_mt[BH_*NKT*S_];                 // running max after tile kt
__device__ __nv_bfloat16 g_qhi[BH_*S_*D_], g_qlo[BH_*S_*D_];
__device__ __nv_bfloat16 g_khi[BH_*S_*D_], g_klo[BH_*S_*D_];
__device__ __nv_bfloat16 g_vthi[BH_*D_*S_], g_vtlo[BH_*D_*S_];   // V^T: [bh][d][k]

// ---------------- helpers ----------------
__device__ __forceinline__ unsigned smem_u32(const void* p){
    unsigned a;
    asm("{ .reg .u64 t; cvta.to.shared.u64 t, %1; cvt.u32.u64 %0, t; }":"=r"(a):"l"(p));
    return a;
}
__device__ __forceinline__ void ldsm_x4(unsigned& a0,unsigned& a1,unsigned& a2,unsigned& a3, unsigned addr){
    asm volatile("ldmatrix.sync.aligned.m8n8.x4.shared.b16 {%0,%1,%2,%3}, [%4];"
        : "=r"(a0),"=r"(a1),"=r"(a2),"=r"(a3) : "r"(addr));
}
__device__ __forceinline__ void ldsm_x2(unsigned& b0,unsigned& b1, unsigned addr){
    asm volatile("ldmatrix.sync.aligned.m8n8.x2.shared.b16 {%0,%1}, [%2];"
        : "=r"(b0),"=r"(b1) : "r"(addr));
}
__device__ __forceinline__ void mma16816(float* c, unsigned a0,unsigned a1,unsigned a2,unsigned a3,
                                         unsigned b0,unsigned b1){
    asm volatile("mma.sync.aligned.m16n8k16.row.col.f32.bf16.bf16.f32 "
        "{%0,%1,%2,%3}, {%4,%5,%6,%7}, {%8,%9}, {%0,%1,%2,%3};"
        : "+f"(c[0]),"+f"(c[1]),"+f"(c[2]),"+f"(c[3])
        : "r"(a0),"r"(a1),"r"(a2),"r"(a3),"r"(b0),"r"(b1));
}
__device__ __forceinline__ void cp16(unsigned saddr, const void* g){
    asm volatile("cp.async.cg.shared.global [%0], [%1], 16;" :: "r"(saddr), "l"(g));
}
#define CP_COMMIT() asm volatile("cp.async.commit_group;" ::: "memory")
#define CP_WAIT(n)  asm volatile("cp.async.wait_group %0;" :: "n"(n) : "memory")

// ---------------- prep: Q,K elementwise hi/lo; V transpose hi/lo ----------------
__global__ __launch_bounds__(256) void prep_kernel(
    const float* __restrict__ Q, const float* __restrict__ K, const float* __restrict__ V)
{
    const int tid = threadIdx.x, bh = blockIdx.y, z = blockIdx.z;
    if (z < 2){
        const float* src = z ? K : Q;
        __nv_bfloat16* dh = z ? g_khi : g_qhi;
        __nv_bfloat16* dl = z ? g_klo : g_qlo;
        size_t base = ((size_t)bh*S_ + blockIdx.x*64)*D_;
        #pragma unroll
        for (int it = 0; it < 8; ++it){
            int i2 = it*256 + tid;
            float2 v = *(const float2*)(src + base + i2*2);
            __nv_bfloat16 h0 = __float2bfloat16(v.x), h1 = __float2bfloat16(v.y);
            __nv_bfloat162 hh; hh.x = h0; hh.y = h1;
            __nv_bfloat162 ll;
            ll.x = __float2bfloat16(v.x - __bfloat162float(h0));
            ll.y = __float2bfloat16(v.y - __bfloat162float(h1));
            *(__nv_bfloat162*)(dh + base + i2*2) = hh;
            *(__nv_bfloat162*)(dl + base + i2*2) = ll;
        }
    } else {
        __shared__ float ts[64][69];
        const int k0 = blockIdx.x * 64;
        #pragma unroll
        for (int it = 0; it < 16; ++it){
            int lin = it*256 + tid;
            int kk = lin >> 6, d = lin & 63;
            ts[kk][d] = V[((size_t)bh*S_ + k0 + kk)*D_ + d];
        }
        __syncthreads();
        #pragma unroll
        for (int it = 0; it < 16; ++it){
            int lin = it*256 + tid;
            int d = lin >> 6, kk = lin & 63;
            float v = ts[kk][d];
            __nv_bfloat16 h = __float2bfloat16(v);
            __nv_bfloat16 l = __float2bfloat16(v - __bfloat162float(h));
            size_t o = ((size_t)bh*D_ + d)*S_ + k0 + kk;
            g_vthi[o] = h;
            g_vtlo[o] = l;
        }
    }
}

// ---------------- pass 1: u = exp(scores - m_kt) via mma.sync bf16x3 ----------------
// smem bf16, row stride 72 elems (144B) => ldmatrix conflict-free, 16B-aligned rows
#define SQ1   72
#define P1_QH 0
#define P1_QL 18432
#define P1_KB 36864        /* two buffers of (KH 18432 + KL 18432) */
#define SMEM1 110592

__global__ __launch_bounds__(256, 2) void scores_mma_kernel(
    const unsigned* __restrict__ mask, const float* __restrict__ adj,
    float* __restrict__ P)
{
    extern __shared__ char smem[];
    const unsigned sb = smem_u32(smem);
    const int tid = threadIdx.x, w = tid >> 5, l = tid & 31;
    const int bh = blockIdx.y, b = bh >> 4;
    const int q0 = blockIdx.x * TQ;

    // prologue: Q hi/lo + K tile 0 via cp.async (group 0)
    {
        const __nv_bfloat16* qh = g_qhi + ((size_t)bh*S_ + q0)*D_;
        const __nv_bfloat16* ql = g_qlo + ((size_t)bh*S_ + q0)*D_;
        #pragma unroll
        for (int it = 0; it < 8; ++it){
            int lin = it*256 + tid;           // 0..2047
            int half = lin >> 10, idx = lin & 1023;
            int row = idx >> 3, g = idx & 7;
            const __nv_bfloat16* src = (half ? ql : qh) + row*D_ + g*8;
            cp16(sb + (half ? P1_QL : P1_QH) + (row*SQ1 + g*8)*2, src);
        }
        const __nv_bfloat16* kh = g_khi + (size_t)bh*S_*D_;
        const __nv_bfloat16* kl = g_klo + (size_t)bh*S_*D_;
        #pragma unroll
        for (int it = 0; it < 8; ++it){
            int lin = it*256 + tid;
            int half = lin >> 10, idx = lin & 1023;
            int row = idx >> 3, g = idx & 7;
            const __nv_bfloat16* src = (half ? kl : kh) + row*D_ + g*8;
            cp16(sb + P1_KB + half*18432 + (row*SQ1 + g*8)*2, src);
        }
        CP_COMMIT();
    }

    const int la_row = 16*w + (l & 15);
    const int la_k8  = (l >> 4) * 8;
    const int lb_row = l & 7;
    const int lb_k8  = ((l >> 3) & 1) * 8;
    const int qr = l >> 2;
    const int ci = l & 3;

    float m_run[2] = {-3.0e38f, -3.0e38f};
    float l_run[2] = {0.f, 0.f};

    for (int kt = 0; kt < NKT; ++kt){
        const int k0 = kt * TK;
        // prefetch next K tile into other buffer
        if (kt + 1 < NKT){
            const __nv_bfloat16* kh = g_khi + ((size_t)bh*S_ + (k0 + TK))*D_;
            const __nv_bfloat16* kl = g_klo + ((size_t)bh*S_ + (k0 + TK))*D_;
            const unsigned kb = sb + P1_KB + ((kt+1)&1)*36864;
            #pragma unroll
            for (int it = 0; it < 8; ++it){
                int lin = it*256 + tid;
                int half = lin >> 10, idx = lin & 1023;
                int row = idx >> 3, g = idx & 7;
                const __nv_bfloat16* src = (half ? kl : kh) + row*D_ + g*8;
                cp16(kb + half*18432 + (row*SQ1 + g*8)*2, src);
            }
            CP_COMMIT();
            CP_WAIT(1);      // current tile (and Q) arrived; next may be in flight
        } else {
            CP_WAIT(0);
        }
        __syncthreads();

        const unsigned kbh = sb + P1_KB + (kt&1)*36864;
        const unsigned kbl = kbh + 18432;

        float acc[16][4];
        #pragma unroll
        for (int nt = 0; nt < 16; ++nt)
            #pragma unroll
            for (int j = 0; j < 4; ++j) acc[nt][j] = 0.f;

        #pragma unroll
        for (int kk = 0; kk < 4; ++kk){
            const int koffA = kk*16 + la_k8;
            unsigned ah0,ah1,ah2,ah3, al0,al1,al2,al3;
            ldsm_x4(ah0,ah1,ah2,ah3, sb + P1_QH + (la_row*SQ1 + koffA)*2);
            ldsm_x4(al0,al1,al2,al3, sb + P1_QL + (la_row*SQ1 + koffA)*2);
            const int koffB = kk*16 + lb_k8;
            #pragma unroll
            for (int nt = 0; nt < 16; ++nt){
                unsigned bh0,bh1, bl0,bl1;
                ldsm_x2(bh0,bh1, kbh + ((8*nt + lb_row)*SQ1 + koffB)*2);
                ldsm_x2(bl0,bl1, kbl + ((8*nt + lb_row)*SQ1 + koffB)*2);
                mma16816(acc[nt], ah0,ah1,ah2,ah3, bh0,bh1);
                mma16816(acc[nt], ah0,ah1,ah2,ah3, bl0,bl1);
                mma16816(acc[nt], al0,al1,al2,al3, bh0,bh1);
            }
        }
        __syncthreads();   // all ldsm of this buffer done; buffer reusable next iter

        // epilogue: bias+scale+mask, online (m,l); store u = exp(s - m_kt)
        #pragma unroll
        for (int h = 0; h < 2; ++h){
            const int row = 16*w + qr + 8*h;
            const float2* ap = (const float2*)(adj + ((size_t)bh*S_ + q0 + row)*S_ + k0);
            const uint2*  mp = (const uint2*) (mask + ((size_t)b*S_  + q0 + row)*S_ + k0);
            float2*       pp = (float2*)(P + ((size_t)bh*S_ + q0 + row)*S_ + k0);
            float s0[16], s1[16];
            float pm = -3.0e38f;
            #pragma unroll
            for (int nt = 0; nt < 16; ++nt){
                float2 a = ap[ci + 4*nt];
                uint2 mv = mp[ci + 4*nt];
                float x0 = (acc[nt][2*h]   + a.x) * 0.125f;
                float x1 = (acc[nt][2*h+1] + a.y) * 0.125f;
                if (mv.x) x0 = __int_as_float(0xff800000u);
                if (mv.y) x1 = __int_as_float(0xff800000u);
                s0[nt] = x0; s1[nt] = x1;
                pm = fmaxf(pm, fmaxf(x0, x1));
            }
            pm = fmaxf(pm, __shfl_xor_sync(0xffffffffu, pm, 1));
            pm = fmaxf(pm, __shfl_xor_sync(0xffffffffu, pm, 2));
            float mn = fmaxf(m_run[h], pm);
            float es = 0.f;
            #pragma unroll
            for (int nt = 0; nt < 16; ++nt){
                s0[nt] = __expf(s0[nt]-mn);
                s1[nt] = __expf(s1[nt]-mn);
                es += s0[nt] + s1[nt];
            }
            es += __shfl_xor_sync(0xffffffffu, es, 1);
            es += __shfl_xor_sync(0xffffffffu, es, 2);
            l_run[h] = l_run[h]*__expf(m_run[h]-mn) + es;
            m_run[h] = mn;
            #pragma unroll
            for (int nt = 0; nt < 16; ++nt)
                pp[ci + 4*nt] = make_float2(s0[nt], s1[nt]);
            if (ci == 0)
                g_mt[((size_t)bh*NKT + kt)*S_ + q0 + row] = mn;
        }
    }

    if (ci == 0){
        #pragma unroll
        for (int h = 0; h < 2; ++h){
            const int row = 16*w + qr + 8*h;
            g_m[bh*S_ + q0 + row] = m_run[h];
            g_l[bh*S_ + q0 + row] = l_run[h];
        }
    }
}

// ---------------- pass 2: p = u*scale; out = P@V via mma.sync bf16x3 ----------------
#define P2_PH 0
#define P2_PL 18432
#define P2_VB 36864        /* two buffers of (VH 9216 + VL 9216) */
#define P2_MS 73728
#define P2_IL 74240
#define SMEM2 74752

__global__ __launch_bounds__(256, 2) void pv_mma_kernel(
    float* __restrict__ P, float* __restrict__ Out)
{
    extern __shared__ char smem[];
    const unsigned sb = smem_u32(smem);
    const int tid = threadIdx.x, w = tid >> 5, l = tid & 31;
    const int bh = blockIdx.y;
    const int q0 = blockIdx.x * TQ;

    float* m_s  = (float*)(smem + P2_MS);
    float* il_s = (float*)(smem + P2_IL);
    if (tid < 128){
        m_s[tid]  = g_m[bh*S_ + q0 + tid];
        il_s[tid] = 1.0f / g_l[bh*S_ + q0 + tid];
    }

    const __nv_bfloat16* vh = g_vthi + (size_t)bh*D_*S_;
    const __nv_bfloat16* vl = g_vtlo + (size_t)bh*D_*S_;

    // prologue: V tile 0
    #pragma unroll
    for (int it = 0; it < 4; ++it){
        int lin = it*256 + tid;           // 0..1023
        int half = lin >> 9, idx = lin & 511;
        int row = idx >> 3, g = idx & 7;  // row = d (0..63), 8 chunks of 8 k
        const __nv_bfloat16* src = (half ? vl : vh) + (size_t)row*S_ + g*8;
        cp16(sb + P2_VB + half*9216 + (row*SQ1 + g*8)*2, src);
    }
    CP_COMMIT();

    const int la_row = 16*w + (l & 15);
    const int la_k8  = (l >> 4) * 8;
    const int lb_row = l & 7;
    const int lb_k8  = ((l >> 3) & 1) * 8;
    const int qr = l >> 2;
    const int ci = l & 3;

    float acc[8][4];
    #pragma unroll
    for (int nt = 0; nt < 8; ++nt)
        #pragma unroll
        for (int j = 0; j < 4; ++j) acc[nt][j] = 0.f;

    __syncthreads();   // m_s/il_s visible

    for (int kt = 0; kt < NKT2; ++kt){
        const int k0 = kt * TK2;
        // prefetch next V tile
        if (kt + 1 < NKT2){
            const unsigned vb = sb + P2_VB + ((kt+1)&1)*18432;
            #pragma unroll
            for (int it = 0; it < 4; ++it){
                int lin = it*256 + tid;
                int half = lin >> 9, idx = lin & 511;
                int row = idx >> 3, g = idx & 7;
                const __nv_bfloat16* src = (half ? vl : vh) + (size_t)row*S_ + k0 + TK2 + g*8;
                cp16(vb + half*9216 + (row*SQ1 + g*8)*2, src);
            }
            CP_COMMIT();
        }

        // P tile: p = u * exp(m_kt - m_fin) * il ; write p ; convert hi/lo to smem
        #pragma unroll
        for (int it = 0; it < 4; ++it){
            int lin = it*256 + tid;        // 0..1023
            int row = lin >> 3, g = lin & 7;
            float mt = g_mt[((size_t)bh*NKT + (kt>>1))*S_ + q0 + row];
            float sc = __expf(mt - m_s[row]) * il_s[row];
            float* sp = P + ((size_t)bh*S_ + q0 + row)*S_ + k0 + g*8;
            float4 x0 = ((const float4*)sp)[0];
            float4 x1 = ((const float4*)sp)[1];
            float4 p0 = make_float4(x0.x*sc, x0.y*sc, x0.z*sc, x0.w*sc);
            float4 p1 = make_float4(x1.x*sc, x1.y*sc, x1.z*sc, x1.w*sc);
            ((float4*)sp)[0] = p0;
            ((float4*)sp)[1] = p1;
            float v[8] = {p0.x,p0.y,p0.z,p0.w,p1.x,p1.y,p1.z,p1.w};
            unsigned hh[4], ll[4];
            #pragma unroll
            for (int i = 0; i < 4; ++i){
                float a = v[2*i], bq = v[2*i+1];
                __nv_bfloat16 ha = __float2bfloat16(a), hb = __float2bfloat16(bq);
                float la = a - __bfloat162float(ha);
                float lb = bq - __bfloat162float(hb);
                hh[i] = ((unsigned)__bfloat16_as_ushort(hb) << 16) | (unsigned)__bfloat16_as_ushort(ha);
                ll[i] = ((unsigned)__bfloat16_as_ushort(__float2bfloat16(lb)) << 16)
                      |  (unsigned)__bfloat16_as_ushort(__float2bfloat16(la));
            }
            *(uint4*)(smem + P2_PH + (row*SQ1 + g*8)*2) = make_uint4(hh[0],hh[1],hh[2],hh[3]);
            *(uint4*)(smem + P2_PL + (row*SQ1 + g*8)*2) = make_uint4(ll[0],ll[1],ll[2],ll[3]);
        }
        if (kt + 1 < NKT2) { CP_WAIT(1); } else { CP_WAIT(0); }
        __syncthreads();

        const unsigned vbh = sb + P2_VB + (kt&1)*18432;
        const unsigned vbl = vbh + 9216;
        #pragma unroll
        for (int kk = 0; kk < 4; ++kk){
            const int koffA = kk*16 + la_k8;
            unsigned ah0,ah1,ah2,ah3, al0,al1,al2,al3;
            ldsm_x4(ah0,ah1,ah2,ah3, sb + P2_PH + (la_row*SQ1 + koffA)*2);
            ldsm_x4(al0,al1,al2,al3, sb + P2_PL + (la_row*SQ1 + koffA)*2);
            const int koffB = kk*16 + lb_k8;
            #pragma unroll
            for (int nt = 0; nt < 8; ++nt){
                unsigned bh0,bh1, bl0,bl1;
                ldsm_x2(bh0,bh1, vbh + ((8*nt + lb_row)*SQ1 + koffB)*2);
                ldsm_x2(bl0,bl1, vbl + ((8*nt + lb_row)*SQ1 + koffB)*2);
                mma16816(acc[nt], ah0,ah1,ah2,ah3, bh0,bh1);
                mma16816(acc[nt], ah0,ah1,ah2,ah3, bl0,bl1);
                mma16816(acc[nt], al0,al1,al2,al3, bh0,bh1);
            }
        }
        __syncthreads();   // PH/PL + V buffer free for next tile
    }

    #pragma unroll
    for (int h = 0; h < 2; ++h){
        const int row = 16*w + qr + 8*h;
        float2* op = (float2*)(Out + ((size_t)bh*S_ + q0 + row)*D_);
        #pragma unroll
        for (int nt = 0; nt < 8; ++nt)
            op[ci + 4*nt] = make_float2(acc[nt][2*h], acc[nt][2*h+1]);
    }
}

// ---------------------------------------------------------------------------
extern "C" void kernel_launch(void* const* d_in, const int* in_sizes, int n_in,
                              void* d_out, int out_size) {
    const float*    Q    = (const float*)d_in[0];
    const float*    K    = (const float*)d_in[1];
    const float*    V    = (const float*)d_in[2];
    const unsigned* mask = (const unsigned*)d_in[3];
    const float*    adj  = (const float*)d_in[4];

    float* out = (float*)d_out;                       // (B,H,S,D)
    float* P   = out + (size_t)B_ * H_ * S_ * D_;     // (B,H,S,S)

    cudaFuncSetAttribute(scores_mma_kernel, cudaFuncAttributeMaxDynamicSharedMemorySize, SMEM1);
    cudaFuncSetAttribute(pv_mma_kernel,     cudaFuncAttributeMaxDynamicSharedMemorySize, SMEM2);

    prep_kernel<<<dim3(S_/64, BH_, 3), 256>>>(Q, K, V);
    dim3 grid(S_/TQ, BH_);   // (16, 32)
    scores_mma_kernel<<<grid, 256, SMEM1>>>(mask, adj, P);
    pv_mma_kernel<<<grid, 256, SMEM2>>>(P, out);
}

// round 14
// speedup vs baseline: 1.0365x; 1.0365x over previous
#include <cuda_runtime.h>
#include <cuda_bf16.h>
#include <cstdint>
#include <cstddef>

#define S_  2048
#define D_  64
#define H_  16
#define B_  2
#define BH_ 32
#define TQ  128
#define TK  128
#define NKT (S_/TK)

// ---------------- device scratch (allocation-free rule) ----------------
__device__ __nv_bfloat16 g_qhi[BH_*S_*D_], g_qlo[BH_*S_*D_];
__device__ __nv_bfloat16 g_khi[BH_*S_*D_], g_klo[BH_*S_*D_];
__device__ __nv_bfloat16 g_vthi[BH_*D_*S_], g_vtlo[BH_*D_*S_];   // V^T: [bh][d][k]

// ---------------- helpers ----------------
__device__ __forceinline__ unsigned smem_u32(const void* p){
    unsigned a;
    asm("{ .reg .u64 t; cvta.to.shared.u64 t, %1; cvt.u32.u64 %0, t; }":"=r"(a):"l"(p));
    return a;
}
__device__ __forceinline__ void ldsm_x4(unsigned& a0,unsigned& a1,unsigned& a2,unsigned& a3, unsigned addr){
    asm volatile("ldmatrix.sync.aligned.m8n8.x4.shared.b16 {%0,%1,%2,%3}, [%4];"
        : "=r"(a0),"=r"(a1),"=r"(a2),"=r"(a3) : "r"(addr));
}
__device__ __forceinline__ void ldsm_x2(unsigned& b0,unsigned& b1, unsigned addr){
    asm volatile("ldmatrix.sync.aligned.m8n8.x2.shared.b16 {%0,%1}, [%2];"
        : "=r"(b0),"=r"(b1) : "r"(addr));
}
__device__ __forceinline__ void mma16816(float* c, unsigned a0,unsigned a1,unsigned a2,unsigned a3,
                                         unsigned b0,unsigned b1){
    asm volatile("mma.sync.aligned.m16n8k16.row.col.f32.bf16.bf16.f32 "
        "{%0,%1,%2,%3}, {%4,%5,%6,%7}, {%8,%9}, {%0,%1,%2,%3};"
        : "+f"(c[0]),"+f"(c[1]),"+f"(c[2]),"+f"(c[3])
        : "r"(a0),"r"(a1),"r"(a2),"r"(a3),"r"(b0),"r"(b1));
}
__device__ __forceinline__ void cp16(unsigned saddr, const void* g){
    asm volatile("cp.async.cg.shared.global [%0], [%1], 16;" :: "r"(saddr), "l"(g));
}
#define CP_COMMIT() asm volatile("cp.async.commit_group;" ::: "memory")
#define CP_WAIT(n)  asm volatile("cp.async.wait_group %0;" :: "n"(n) : "memory")

// pack two floats -> bf16x2 hi and bf16x2 lo-residual
__device__ __forceinline__ void hilo2(float a, float b, unsigned& h, unsigned& lo){
    __nv_bfloat16 ha = __float2bfloat16(a), hb = __float2bfloat16(b);
    h  = ((unsigned)__bfloat16_as_ushort(hb) << 16) | (unsigned)__bfloat16_as_ushort(ha);
    __nv_bfloat16 la = __float2bfloat16(a - __bfloat162float(ha));
    __nv_bfloat16 lb = __float2bfloat16(b - __bfloat162float(hb));
    lo = ((unsigned)__bfloat16_as_ushort(lb) << 16) | (unsigned)__bfloat16_as_ushort(la);
}

// ---------------- prep: Q,K elementwise hi/lo; V transpose hi/lo ----------------
__global__ __launch_bounds__(256) void prep_kernel(
    const float* __restrict__ Q, const float* __restrict__ K, const float* __restrict__ V)
{
    const int tid = threadIdx.x, bh = blockIdx.y, z = blockIdx.z;
    if (z < 2){
        const float* src = z ? K : Q;
        __nv_bfloat16* dh = z ? g_khi : g_qhi;
        __nv_bfloat16* dl = z ? g_klo : g_qlo;
        size_t base = ((size_t)bh*S_ + blockIdx.x*64)*D_;
        #pragma unroll
        for (int it = 0; it < 8; ++it){
            int i2 = it*256 + tid;
            float2 v = *(const float2*)(src + base + i2*2);
            __nv_bfloat16 h0 = __float2bfloat16(v.x), h1 = __float2bfloat16(v.y);
            __nv_bfloat162 hh; hh.x = h0; hh.y = h1;
            __nv_bfloat162 ll;
            ll.x = __float2bfloat16(v.x - __bfloat162float(h0));
            ll.y = __float2bfloat16(v.y - __bfloat162float(h1));
            *(__nv_bfloat162*)(dh + base + i2*2) = hh;
            *(__nv_bfloat162*)(dl + base + i2*2) = ll;
        }
    } else {
        __shared__ float ts[64][69];
        const int k0 = blockIdx.x * 64;
        #pragma unroll
        for (int it = 0; it < 16; ++it){
            int lin = it*256 + tid;
            int kk = lin >> 6, d = lin & 63;
            ts[kk][d] = V[((size_t)bh*S_ + k0 + kk)*D_ + d];
        }
        __syncthreads();
        #pragma unroll
        for (int it = 0; it < 16; ++it){
            int lin = it*256 + tid;
            int d = lin >> 6, kk = lin & 63;
            float v = ts[kk][d];
            __nv_bfloat16 h = __float2bfloat16(v);
            __nv_bfloat16 l = __float2bfloat16(v - __bfloat162float(h));
            size_t o = ((size_t)bh*D_ + d)*S_ + k0 + kk;
            g_vthi[o] = h;
            g_vtlo[o] = l;
        }
    }
}

// ---------------- fused attention ----------------
// smem layout (bytes). Q/K rows: 64 elems stride SQ1=72 (144B, +4 banks/row).
// V^T rows: 128 elems stride SV=136 (272B, +4 banks/row).
#define SQ1   72
#define SV    136
#define F_QH  0
#define F_QL  18432
#define F_KH  36864
#define F_KL  55296
#define F_VH  73728
#define F_VL  91136
#define F_MT  108544     /* per-tile row max: [16][128] fp32 = 8192 */
#define F_MS  116736     /* final m per row: 512 */
#define F_IL  117248     /* 1/l per row: 512 */
#define SMEMF 117760

__global__ __launch_bounds__(256) void fused_attn_kernel(
    const unsigned* __restrict__ mask, const float* __restrict__ adj,
    float* __restrict__ P, float* __restrict__ Out)
{
    extern __shared__ char smem[];
    const unsigned sb = smem_u32(smem);
    const int tid = threadIdx.x, w = tid >> 5, l = tid & 31;
    const int bh = blockIdx.y, b = bh >> 4;
    const int q0 = blockIdx.x * TQ;

    // prologue: Q hi/lo via cp.async
    {
        const __nv_bfloat16* qh = g_qhi + ((size_t)bh*S_ + q0)*D_;
        const __nv_bfloat16* ql = g_qlo + ((size_t)bh*S_ + q0)*D_;
        #pragma unroll
        for (int it = 0; it < 8; ++it){
            int lin = it*256 + tid;           // 0..2047
            int half = lin >> 10, idx = lin & 1023;
            int row = idx >> 3, g = idx & 7;
            cp16(sb + (half ? F_QL : F_QH) + (row*SQ1 + g*8)*2,
                 (half ? ql : qh) + row*D_ + g*8);
        }
        CP_COMMIT();
    }

    const __nv_bfloat16* kh_g = g_khi + (size_t)bh*S_*D_;
    const __nv_bfloat16* kl_g = g_klo + (size_t)bh*S_*D_;
    const __nv_bfloat16* vh_g = g_vthi + (size_t)bh*D_*S_;
    const __nv_bfloat16* vl_g = g_vtlo + (size_t)bh*D_*S_;

    const int la_row = 16*w + (l & 15);
    const int la_k8  = (l >> 4) * 8;
    const int lb_row = l & 7;
    const int lb_k8  = ((l >> 3) & 1) * 8;
    const int qr = l >> 2;
    const int ci = l & 3;

    float m_run[2] = {-3.0e38f, -3.0e38f};
    float l_run[2] = {0.f, 0.f};
    float oacc[8][4];
    #pragma unroll
    for (int dg = 0; dg < 8; ++dg)
        #pragma unroll
        for (int j = 0; j < 4; ++j) oacc[dg][j] = 0.f;

    float* sm_mt = (float*)(smem + F_MT);

    for (int kt = 0; kt < NKT; ++kt){
        const int k0 = kt * TK;
        // K tile hi/lo
        #pragma unroll
        for (int it = 0; it < 8; ++it){
            int lin = it*256 + tid;
            int half = lin >> 10, idx = lin & 1023;
            int row = idx >> 3, g = idx & 7;
            cp16(sb + (half ? F_KL : F_KH) + (row*SQ1 + g*8)*2,
                 (half ? kl_g : kh_g) + (size_t)(k0 + row)*D_ + g*8);
        }
        // V^T tile hi/lo: [64 d][128 k]
        #pragma unroll
        for (int it = 0; it < 8; ++it){
            int lin = it*256 + tid;
            int half = lin >> 10, idx = lin & 1023;
            int row = idx >> 4, g = idx & 15;
            cp16(sb + (half ? F_VL : F_VH) + (row*SV + g*8)*2,
                 (half ? vl_g : vh_g) + (size_t)row*S_ + k0 + g*8);
        }
        CP_COMMIT(); CP_WAIT(0);
        __syncthreads();

        // ---- QK^T ----
        float acc[16][4];
        #pragma unroll
        for (int nt = 0; nt < 16; ++nt)
            #pragma unroll
            for (int j = 0; j < 4; ++j) acc[nt][j] = 0.f;

        #pragma unroll
        for (int kk = 0; kk < 4; ++kk){
            const int koffA = kk*16 + la_k8;
            unsigned ah0,ah1,ah2,ah3, al0,al1,al2,al3;
            ldsm_x4(ah0,ah1,ah2,ah3, sb + F_QH + (la_row*SQ1 + koffA)*2);
            ldsm_x4(al0,al1,al2,al3, sb + F_QL + (la_row*SQ1 + koffA)*2);
            const int koffB = kk*16 + lb_k8;
            #pragma unroll
            for (int nt = 0; nt < 16; ++nt){
                unsigned bh0,bh1, bl0,bl1;
                ldsm_x2(bh0,bh1, sb + F_KH + ((8*nt + lb_row)*SQ1 + koffB)*2);
                ldsm_x2(bl0,bl1, sb + F_KL + ((8*nt + lb_row)*SQ1 + koffB)*2);
                mma16816(acc[nt], ah0,ah1,ah2,ah3, bh0,bh1);
                mma16816(acc[nt], ah0,ah1,ah2,ah3, bl0,bl1);
                mma16816(acc[nt], al0,al1,al2,al3, bh0,bh1);
            }
        }

        // ---- epilogue: bias+scale+mask, online (m,l), u=exp(s-m_kt), O rescale ----
        float e0[16], e1[16], f0[16], f1[16];   // u for h=0 (e) and h=1 (f)
        #pragma unroll
        for (int h = 0; h < 2; ++h){
            const int row = 16*w + qr + 8*h;
            const float2* ap = (const float2*)(adj + ((size_t)bh*S_ + q0 + row)*S_ + k0);
            const uint2*  mp = (const uint2*) (mask + ((size_t)b*S_  + q0 + row)*S_ + k0);
            float2*       pp = (float2*)(P + ((size_t)bh*S_ + q0 + row)*S_ + k0);
            float* u0 = h ? f0 : e0;
            float* u1 = h ? f1 : e1;
            float pm = -3.0e38f;
            #pragma unroll
            for (int nt = 0; nt < 16; ++nt){
                float2 a = ap[ci + 4*nt];
                uint2 mv = mp[ci + 4*nt];
                float x0 = (acc[nt][2*h]   + a.x) * 0.125f;
                float x1 = (acc[nt][2*h+1] + a.y) * 0.125f;
                if (mv.x) x0 = __int_as_float(0xff800000u);
                if (mv.y) x1 = __int_as_float(0xff800000u);
                u0[nt] = x0; u1[nt] = x1;
                pm = fmaxf(pm, fmaxf(x0, x1));
            }
            pm = fmaxf(pm, __shfl_xor_sync(0xffffffffu, pm, 1));
            pm = fmaxf(pm, __shfl_xor_sync(0xffffffffu, pm, 2));
            float mn = fmaxf(m_run[h], pm);
            float corr = __expf(m_run[h] - mn);
            float es = 0.f;
            #pragma unroll
            for (int nt = 0; nt < 16; ++nt){
                u0[nt] = __expf(u0[nt] - mn);
                u1[nt] = __expf(u1[nt] - mn);
                es += u0[nt] + u1[nt];
            }
            es += __shfl_xor_sync(0xffffffffu, es, 1);
            es += __shfl_xor_sync(0xffffffffu, es, 2);
            l_run[h] = l_run[h]*corr + es;
            m_run[h] = mn;
            #pragma unroll
            for (int dg = 0; dg < 8; ++dg){
                oacc[dg][2*h]   *= corr;
                oacc[dg][2*h+1] *= corr;
            }
            #pragma unroll
            for (int nt = 0; nt < 16; ++nt)
                pp[ci + 4*nt] = make_float2(u0[nt], u1[nt]);
            if (ci == 0)
                sm_mt[kt*128 + row] = mn;
        }

        // ---- PV: O += u @ V  (u fragments straight from registers) ----
        #pragma unroll
        for (int kb = 0; kb < 8; ++kb){
            unsigned ah0,al0, ah1,al1, ah2,al2, ah3,al3;
            hilo2(e0[2*kb],   e1[2*kb],   ah0, al0);
            hilo2(f0[2*kb],   f1[2*kb],   ah1, al1);
            hilo2(e0[2*kb+1], e1[2*kb+1], ah2, al2);
            hilo2(f0[2*kb+1], f1[2*kb+1], ah3, al3);
            const int koffB = kb*16 + lb_k8;
            #pragma unroll
            for (int dg = 0; dg < 8; ++dg){
                unsigned vh0,vh1, vl0,vl1;
                ldsm_x2(vh0,vh1, sb + F_VH + ((8*dg + lb_row)*SV + koffB)*2);
                ldsm_x2(vl0,vl1, sb + F_VL + ((8*dg + lb_row)*SV + koffB)*2);
                mma16816(oacc[dg], ah0,ah1,ah2,ah3, vh0,vh1);
                mma16816(oacc[dg], ah0,ah1,ah2,ah3, vl0,vl1);
                mma16816(oacc[dg], al0,al1,al2,al3, vh0,vh1);
            }
        }
        __syncthreads();   // all smem consumers done before next tile's loads
    }

    // ---- write O = oacc / l ----
    #pragma unroll
    for (int h = 0; h < 2; ++h){
        const int row = 16*w + qr + 8*h;
        const float inv = 1.0f / l_run[h];
        float2* op = (float2*)(Out + ((size_t)bh*S_ + q0 + row)*D_);
        #pragma unroll
        for (int dg = 0; dg < 8; ++dg)
            op[ci + 4*dg] = make_float2(oacc[dg][2*h]*inv, oacc[dg][2*h+1]*inv);
    }

    // ---- publish m/il, then rescale this CTA's P stripe in place ----
    float* sm_m  = (float*)(smem + F_MS);
    float* sm_il = (float*)(smem + F_IL);
    if (ci == 0){
        #pragma unroll
        for (int h = 0; h < 2; ++h){
            const int row = 16*w + qr + 8*h;
            sm_m[row]  = m_run[h];
            sm_il[row] = 1.0f / l_run[h];
        }
    }
    __syncthreads();   // m/il + all P(u) gmem writes visible block-wide

    #pragma unroll
    for (int j = 0; j < 16; ++j){
        const int lr = 8*j + w;              // 0..127
        const float m  = sm_m[lr];
        const float il = sm_il[lr];
        float4* pr = (float4*)(P + ((size_t)bh*S_ + q0 + lr)*S_);
        #pragma unroll
        for (int kt = 0; kt < NKT; ++kt){
            float sc = __expf(sm_mt[kt*128 + lr] - m) * il;
            float4 v = pr[kt*32 + l];
            v.x *= sc; v.y *= sc; v.z *= sc; v.w *= sc;
            pr[kt*32 + l] = v;
        }
    }
}

// ---------------------------------------------------------------------------
extern "C" void kernel_launch(void* const* d_in, const int* in_sizes, int n_in,
                              void* d_out, int out_size) {
    const float*    Q    = (const float*)d_in[0];
    const float*    K    = (const float*)d_in[1];
    const float*    V    = (const float*)d_in[2];
    const unsigned* mask = (const unsigned*)d_in[3];
    const float*    adj  = (const float*)d_in[4];

    float* out = (float*)d_out;                       // (B,H,S,D)
    float* P   = out + (size_t)B_ * H_ * S_ * D_;     // (B,H,S,S)

    cudaFuncSetAttribute(fused_attn_kernel, cudaFuncAttributeMaxDynamicSharedMemorySize, SMEMF);

    prep_kernel<<<dim3(S_/64, BH_, 3), 256>>>(Q, K, V);
    fused_attn_kernel<<<dim3(S_/TQ, BH_), 256, SMEMF>>>(mask, adj, P, out);
}